// round 17
// baseline (speedup 1.0000x reference)
#include <cuda_runtime.h>
#include <cstdint>

#define NB 64
#define NT 1024
#define NI 256
#define NH 512
#define NO 256

// ---------------- scratch (device globals: the sanctioned no-alloc path) ----------------
__device__ float g_xh[(size_t)NB * NT * NH];   // 128 MB: [t][b][h]
__device__ float g_hs[(size_t)NB * NT * NH];   // 128 MB: [b][t][h]
__device__ unsigned g_prog[16];                // per-cluster scan progress (chunks*8)
__device__ unsigned g_probe;                   // dummy target

// ---------------- helpers ----------------
__device__ __forceinline__ void fma2(unsigned long long& d, unsigned long long a,
                                     unsigned long long b) {
    asm("fma.rn.f32x2 %0, %1, %2, %0;" : "+l"(d) : "l"(a), "l"(b));
}
__device__ __forceinline__ unsigned long long pack2(float lo, float hi) {
    unsigned long long v;
    asm("mov.b64 %0, {%1, %2};" : "=l"(v) : "f"(lo), "f"(hi));
    return v;
}
__device__ __forceinline__ float f2sum(unsigned long long v) {
    float lo, hi;
    asm("mov.b64 {%0, %1}, %2;" : "=f"(lo), "=f"(hi) : "l"(v));
    return lo + hi;
}
__device__ __forceinline__ unsigned smem_u32(const void* p) {
    unsigned a;
    asm("{ .reg .u64 t; cvta.to.shared.u64 t, %1; cvt.u32.u64 %0, t; }"
        : "=r"(a) : "l"(p));
    return a;
}
__device__ __forceinline__ void mbar_init(unsigned a, unsigned cnt) {
    asm volatile("mbarrier.init.shared.b64 [%0], %1;" ::"r"(a), "r"(cnt) : "memory");
}
__device__ __forceinline__ void mbar_arrive_expect_tx(unsigned a, unsigned bytes) {
    asm volatile("mbarrier.arrive.expect_tx.shared.b64 _, [%0], %1;"
                 ::"r"(a), "r"(bytes) : "memory");
}
__device__ __forceinline__ void mbar_wait_parity(unsigned a, unsigned parity) {
    unsigned done;
    asm volatile(
        "{\n\t.reg .pred p;\n\t"
        "mbarrier.try_wait.parity.acquire.cta.shared::cta.b64 p, [%1], %2;\n\t"
        "selp.b32 %0, 1, 0, p;\n\t}"
        : "=r"(done) : "r"(a), "r"(parity) : "memory");
    if (!done) {
        asm volatile(
            "{\n\t.reg .pred P1;\n\t"
            "WAIT_LOOP_%=:\n\t"
            "mbarrier.try_wait.parity.acquire.cta.shared::cta.b64 P1, [%0], %1, 0x989680;\n\t"
            "@P1 bra.uni WAIT_DONE_%=;\n\t"
            "bra.uni WAIT_LOOP_%=;\n\t"
            "WAIT_DONE_%=:\n\t}"
            ::"r"(a), "r"(parity) : "memory");
    }
}
__device__ __forceinline__ void st_async_b64(unsigned addr, unsigned long long v,
                                             unsigned mbar) {
    asm volatile(
        "st.async.shared::cluster.mbarrier::complete_tx::bytes.b64 [%0], %1, [%2];"
        ::"r"(addr), "l"(v), "r"(mbar) : "memory");
}
__device__ __forceinline__ unsigned ld_acquire_u32(const unsigned* p) {
    unsigned v;
    asm volatile("ld.acquire.gpu.u32 %0, [%1];" : "=r"(v) : "l"(p) : "memory");
    return v;
}
// fast tanh: 1 - 2/(e^{2v}+1). Correct limits at +/-inf; err ~1e-6.
__device__ __forceinline__ float tanh_fast(float v) {
    float e = __expf(2.0f * v);
    return 1.0f - __fdividef(2.0f, e + 1.0f);
}

// probe: zeroes the progress flags before each mega replay
__global__ void probe_kernel() {
    if (threadIdx.x < 16) g_prog[threadIdx.x] = 0u;
    if (threadIdx.x == 0) g_probe = 0u;
}

// =====================================================================================
// GEMM0 v4 (R12-proven): xh = x @ W_xh + b_h. BM=128, BN=64, BK=32, 8x4 tile,
// f32x2, cp.async double-buffered, one __syncthreads per k-tile.
// =====================================================================================
#define ASZ (128 * 36)
#define BSZ (64 * 36)

__global__ __launch_bounds__(256, 2) void gemm0_kernel(const float* __restrict__ A,
                                                       const float* __restrict__ Bm,
                                                       const float* __restrict__ bias) {
    extern __shared__ __align__(16) float gsm[];
    float* As = gsm;
    float* Bs = gsm + 2 * ASZ;

    const int tid = threadIdx.x;
    const int tn = tid & 15, tm = tid >> 4;
    const int n0 = blockIdx.x * 64;
    const int m0 = blockIdx.y * 128;
    const int N = NH;   // 512
    const int K = NI;   // 256

    const unsigned as_base = smem_u32(As);

    unsigned long long acc[8][4];
#pragma unroll
    for (int i = 0; i < 8; i++)
#pragma unroll
        for (int j = 0; j < 4; j++) acc[i][j] = 0ULL;

    const int a_m = tid >> 1, a_s = (tid & 1) * 16;
    const int b_k = tid >> 3, b_s = (tid & 7) * 8;

    auto issueA = [&](int k0, int b) {
        const float* ap = &A[(size_t)(m0 + a_m) * K + k0 + a_s];
        unsigned dst = as_base + (unsigned)(b * ASZ + a_m * 36 + a_s) * 4u;
#pragma unroll
        for (int ch = 0; ch < 4; ch++)
            asm volatile("cp.async.cg.shared.global [%0], [%1], 16;"
                         ::"r"(dst + ch * 16), "l"(ap + ch * 4) : "memory");
    };
    auto stsB = [&](int b, float4 v0, float4 v1) {
        float* B = Bs + b * BSZ;
        B[(b_s + 0) * 36 + b_k] = v0.x;
        B[(b_s + 1) * 36 + b_k] = v0.y;
        B[(b_s + 2) * 36 + b_k] = v0.z;
        B[(b_s + 3) * 36 + b_k] = v0.w;
        B[(b_s + 4) * 36 + b_k] = v1.x;
        B[(b_s + 5) * 36 + b_k] = v1.y;
        B[(b_s + 6) * 36 + b_k] = v1.z;
        B[(b_s + 7) * 36 + b_k] = v1.w;
    };

    {
        issueA(0, 0);
        asm volatile("cp.async.commit_group;" ::: "memory");
        const float* bp = &Bm[(size_t)b_k * N + n0 + b_s];
        float4 v0 = *(const float4*)bp;
        float4 v1 = *(const float4*)(bp + 4);
        asm volatile("cp.async.wait_group 0;" ::: "memory");
        stsB(0, v0, v1);
        __syncthreads();
    }

    int buf = 0;
    for (int k0 = 0; k0 < K; k0 += 32) {
        const int nxt = buf ^ 1;
        const bool more = (k0 + 32 < K);
        float4 nb0, nb1;
        if (more) {
            issueA(k0 + 32, nxt);
            asm volatile("cp.async.commit_group;" ::: "memory");
            const float* bp = &Bm[(size_t)(k0 + 32 + b_k) * N + n0 + b_s];
            nb0 = *(const float4*)bp;
            nb1 = *(const float4*)(bp + 4);
        }
        const float* Ab = As + buf * ASZ;
        const float* Bb = Bs + buf * BSZ;
#pragma unroll
        for (int kk = 0; kk < 32; kk += 4) {
            ulonglong2 bv[4];
#pragma unroll
            for (int j = 0; j < 4; j++)
                bv[j] = *(const ulonglong2*)&Bb[(tn + 16 * j) * 36 + kk];
#pragma unroll
            for (int i = 0; i < 8; i++) {
                ulonglong2 av = *(const ulonglong2*)&Ab[(tm + 16 * i) * 36 + kk];
#pragma unroll
                for (int j = 0; j < 4; j++) {
                    fma2(acc[i][j], av.x, bv[j].x);
                    fma2(acc[i][j], av.y, bv[j].y);
                }
            }
        }
        if (more) {
            asm volatile("cp.async.wait_group 0;" ::: "memory");
            stsB(nxt, nb0, nb1);
        }
        __syncthreads();
        buf = nxt;
    }

#pragma unroll
    for (int j = 0; j < 4; j++) {
        int n = n0 + tn + 16 * j;
        float bz = bias[n];
#pragma unroll
        for (int i = 0; i < 8; i++) {
            int m = m0 + tm + 16 * i;
            float v = f2sum(acc[i][j]) + bz;
            int b = m >> 10, t = m & 1023;
            g_xh[((size_t)t * NB + b) * NH + n] = v;
        }
    }
}

// =====================================================================================
// MEGA kernel: bids 0..127 = scan (R12 skeleton + 8-way k-split, tree reduce,
// fast tanh); bids 128..2175 = gemm<1> tiles gated on g_prog (unchanged).
// Scan mapping: cc = tid&31 (32 cols), ks = tid>>5 (8 k-splits of 64) == warp
// id == consumed slice; thread covers 4 rows x 2 cols x 64 k (same 512 MACs,
// same 128 W-floats in regs). Reduction: 8 partials, pairwise tree.
// =====================================================================================
__global__ __launch_bounds__(256) __cluster_dims__(8, 1, 1)
void mega_kernel(const float* __restrict__ W_hh, const float* __restrict__ W_hy,
                 const float* __restrict__ b_y, float* __restrict__ out) {
    extern __shared__ __align__(16) float smem[];

    const int tid = threadIdx.x;

    if (blockIdx.x < 128) {
        // ======================= SCAN branch =======================
        float* hsm = smem;                // [2][4][516]
        float* red = smem + 2 * 4 * 516;  // [2][8*4][64]
        __shared__ __align__(8) unsigned long long mbar[8];

        unsigned s;
        asm("mov.u32 %0, %%cluster_ctarank;" : "=r"(s));
        const int g = blockIdx.x >> 3;
        const int cc = tid & 31, ks = tid >> 5;      // 32 cols x 8 k-splits
        const int rr = tid >> 6, c = tid & 63;       // reduce/io mapping
        const int w = tid >> 5;                      // warp id == slice consumed

        const unsigned mbar_base = smem_u32(mbar);
        const unsigned hsm_base = smem_u32(hsm);
        const int k0 = ks * 64;

        // W block in regs: 2 cols x 64 k = 64 f32x2 pairs (128 f32)
        unsigned long long wreg[2][32];
#pragma unroll
        for (int cp = 0; cp < 2; cp++) {
            const float* wp = &W_hh[(size_t)k0 * NH + s * 64 + cc + 32 * cp];
#pragma unroll 4
            for (int j = 0; j < 32; j++) {
                float w0 = __ldg(wp + (size_t)(2 * j) * NH);
                float w1 = __ldg(wp + (size_t)(2 * j + 1) * NH);
                wreg[cp][j] = pack2(w0, w1);
            }
        }

        for (int idx = tid; idx < 2 * 4 * 516; idx += 256) hsm[idx] = 0.f;
        if (tid == 0) {
#pragma unroll
            for (int j = 0; j < 8; j++) {
                mbar_init(mbar_base + j * 8, 1);
                mbar_arrive_expect_tx(mbar_base + j * 8, 1024);
            }
        }
        __syncthreads();

        asm volatile("barrier.cluster.arrive.aligned;" ::: "memory");
        asm volatile("barrier.cluster.wait.aligned;" ::: "memory");

        unsigned remh[8], remb[8];
#pragma unroll
        for (int p = 0; p < 8; p++) {
            asm("mapa.shared::cluster.u32 %0, %1, %2;"
                : "=r"(remh[p]) : "r"(hsm_base), "r"((unsigned)p));
            asm("mapa.shared::cluster.u32 %0, %1, %2;"
                : "=r"(remb[p]) : "r"(mbar_base), "r"((unsigned)p));
        }

        const unsigned my_elem = (unsigned)(rr * 516 + s * 64 + c) * 4u;
        const bool sender = ((c & 1) == 0);
        const unsigned mbar_src_off = s * 8u;
        const float* xp = &g_xh[(size_t)(g * 4 + rr) * NH + s * 64 + c];

        float xval = __ldg(xp);

        for (int t = 0; t < NT; t++) {
            float xnext =
                (t + 1 < NT) ? __ldg(xp + (size_t)(t + 1) * (NB * NH)) : 0.f;

            const float* hcur = hsm + (t & 1) * (4 * 516);
            float* redt = red + (t & 1) * (8 * 4 * 64);

            unsigned long long acc[4][2];
#pragma unroll
            for (int r = 0; r < 4; r++)
#pragma unroll
                for (int cp = 0; cp < 2; cp++) acc[r][cp] = 0ULL;

#pragma unroll
            for (int kk = 0; kk < 64; kk += 4) {
                ulonglong2 hv[4];
#pragma unroll
                for (int r = 0; r < 4; r++)
                    hv[r] = *(const ulonglong2*)&hcur[r * 516 + k0 + kk];
#pragma unroll
                for (int cp = 0; cp < 2; cp++) {
#pragma unroll
                    for (int r = 0; r < 4; r++) {
                        fma2(acc[r][cp], wreg[cp][kk / 2], hv[r].x);
                        fma2(acc[r][cp], wreg[cp][kk / 2 + 1], hv[r].y);
                    }
                }
            }
#pragma unroll
            for (int r = 0; r < 4; r++)
#pragma unroll
                for (int cp = 0; cp < 2; cp++)
                    redt[(ks * 4 + r) * 64 + cc + 32 * cp] = f2sum(acc[r][cp]);
            __syncthreads();  // bar1: red complete

            // 8-term tree reduction + fast tanh
            float a0 = redt[(0 * 4 + rr) * 64 + c], a1 = redt[(1 * 4 + rr) * 64 + c];
            float a2 = redt[(2 * 4 + rr) * 64 + c], a3 = redt[(3 * 4 + rr) * 64 + c];
            float a4 = redt[(4 * 4 + rr) * 64 + c], a5 = redt[(5 * 4 + rr) * 64 + c];
            float a6 = redt[(6 * 4 + rr) * 64 + c], a7 = redt[(7 * 4 + rr) * 64 + c];
            float v = (((a0 + a1) + (a2 + a3)) + ((a4 + a5) + (a6 + a7))) + xval;
            float h = tanh_fast(v);

            if (t + 1 < NT) {
                const unsigned nb = (t + 1) & 1;
                const unsigned boff = nb * (4 * 516 * 4) + my_elem;

                float hn = __shfl_down_sync(0xffffffffu, h, 1);
                hsm[nb * (4 * 516) + rr * 516 + s * 64 + c] = h;

                if (sender) {
                    unsigned long long pair = pack2(h, hn);
#pragma unroll
                    for (int p = 0; p < 8; p++) {
                        if (p != (int)s)
                            st_async_b64(remh[p] + boff, pair,
                                         remb[p] + mbar_src_off);
                    }
                }
            }

            g_hs[((size_t)(g * 4 + rr) * NT + t) * NH + s * 64 + c] = h;

            // progress publish: chunk (t>>7) complete for this CTA's slice
            if ((t & 127) == 127) {
                __threadfence();
                __syncthreads();
                if (tid == 0) atomicAdd(&g_prog[g], 1u);
            }

            if (t + 1 < NT) {
                __syncthreads();  // bar2: own-slice STS visible to warp s
                if (w != (int)s) {
                    if ((tid & 31) == 0) {
                        mbar_wait_parity(mbar_base + w * 8u, (unsigned)(t & 1));
                        mbar_arrive_expect_tx(mbar_base + w * 8u, 1024);
                    }
                    __syncwarp();
                }
            }
            xval = xnext;
        }

        asm volatile("barrier.cluster.arrive.aligned;" ::: "memory");
        asm volatile("barrier.cluster.wait.aligned;" ::: "memory");
        return;
    }

    // ======================= GEMM<1> branch (R12-proven) =======================
    const int tile = blockIdx.x - 128;   // 0..2047
    const int tc = tile >> 8;            // t-chunk 0..7
    const int within = tile & 255;       // 0..255
    const int b = within >> 2;           // batch 0..63
    const int nblk = within & 3;         // n-block 0..3

    if (tid == 0) {
        const unsigned need = 8u * (unsigned)(tc + 1);
        while (ld_acquire_u32(&g_prog[b >> 2]) < need) {
        }
    }
    __syncthreads();

    float* As = smem;
    float* Bs = smem + 2 * ASZ;

    const int tn = tid & 15, tm = tid >> 4;
    const int n0 = nblk * 64;
    const int m0 = b * 1024 + tc * 128;
    const int N = NO;   // 256
    const int K = NH;   // 512

    const float* Ap = (const float*)g_hs;
    const unsigned as_base = smem_u32(As);

    unsigned long long acc[8][4];
#pragma unroll
    for (int i = 0; i < 8; i++)
#pragma unroll
        for (int j = 0; j < 4; j++) acc[i][j] = 0ULL;

    const int a_m = tid >> 1, a_s = (tid & 1) * 16;
    const int b_k = tid >> 3, b_s = (tid & 7) * 8;

    auto issueA = [&](int k0, int bb) {
        const float* ap = &Ap[(size_t)(m0 + a_m) * K + k0 + a_s];
        unsigned dst = as_base + (unsigned)(bb * ASZ + a_m * 36 + a_s) * 4u;
#pragma unroll
        for (int ch = 0; ch < 4; ch++)
            asm volatile("cp.async.cg.shared.global [%0], [%1], 16;"
                         ::"r"(dst + ch * 16), "l"(ap + ch * 4) : "memory");
    };
    auto stsB = [&](int bb, float4 v0, float4 v1) {
        float* B = Bs + bb * BSZ;
        B[(b_s + 0) * 36 + b_k] = v0.x;
        B[(b_s + 1) * 36 + b_k] = v0.y;
        B[(b_s + 2) * 36 + b_k] = v0.z;
        B[(b_s + 3) * 36 + b_k] = v0.w;
        B[(b_s + 4) * 36 + b_k] = v1.x;
        B[(b_s + 5) * 36 + b_k] = v1.y;
        B[(b_s + 6) * 36 + b_k] = v1.z;
        B[(b_s + 7) * 36 + b_k] = v1.w;
    };

    {
        issueA(0, 0);
        asm volatile("cp.async.commit_group;" ::: "memory");
        const float* bp = &W_hy[(size_t)b_k * N + n0 + b_s];
        float4 v0 = *(const float4*)bp;
        float4 v1 = *(const float4*)(bp + 4);
        asm volatile("cp.async.wait_group 0;" ::: "memory");
        stsB(0, v0, v1);
        __syncthreads();
    }

    int buf = 0;
    for (int k0 = 0; k0 < K; k0 += 32) {
        const int nxt = buf ^ 1;
        const bool more = (k0 + 32 < K);
        float4 nb0, nb1;
        if (more) {
            issueA(k0 + 32, nxt);
            asm volatile("cp.async.commit_group;" ::: "memory");
            const float* bp = &W_hy[(size_t)(k0 + 32 + b_k) * N + n0 + b_s];
            nb0 = *(const float4*)bp;
            nb1 = *(const float4*)(bp + 4);
        }
        const float* Ab = As + buf * ASZ;
        const float* Bb = Bs + buf * BSZ;
#pragma unroll
        for (int kk = 0; kk < 32; kk += 4) {
            ulonglong2 bv[4];
#pragma unroll
            for (int j = 0; j < 4; j++)
                bv[j] = *(const ulonglong2*)&Bb[(tn + 16 * j) * 36 + kk];
#pragma unroll
            for (int i = 0; i < 8; i++) {
                ulonglong2 av = *(const ulonglong2*)&Ab[(tm + 16 * i) * 36 + kk];
#pragma unroll
                for (int j = 0; j < 4; j++) {
                    fma2(acc[i][j], av.x, bv[j].x);
                    fma2(acc[i][j], av.y, bv[j].y);
                }
            }
        }
        if (more) {
            asm volatile("cp.async.wait_group 0;" ::: "memory");
            stsB(nxt, nb0, nb1);
        }
        __syncthreads();
        buf = nxt;
    }

#pragma unroll
    for (int j = 0; j < 4; j++) {
        int n = n0 + tn + 16 * j;
        float bz = b_y[n];
#pragma unroll
        for (int i = 0; i < 8; i++) {
            int m = m0 + tm + 16 * i;
            out[(size_t)m * NO + n] = f2sum(acc[i][j]) + bz;
        }
    }
}

// =====================================================================================
extern "C" void kernel_launch(void* const* d_in, const int* in_sizes, int n_in,
                              void* d_out, int out_size) {
    const float* x = (const float*)d_in[0];
    const float* W_xh = (const float*)d_in[1];
    const float* W_hh = (const float*)d_in[2];
    const float* b_h = (const float*)d_in[3];
    const float* W_hy = (const float*)d_in[4];
    const float* b_y = (const float*)d_in[5];
    float* out = (float*)d_out;

    const int gemm_smem = (2 * ASZ + 2 * BSZ) * (int)sizeof(float);  // 55.3 KB
    cudaFuncSetAttribute(gemm0_kernel, cudaFuncAttributeMaxDynamicSharedMemorySize,
                         gemm_smem);
    cudaFuncSetAttribute(mega_kernel, cudaFuncAttributeMaxDynamicSharedMemorySize,
                         gemm_smem);

    probe_kernel<<<1, 32>>>();                                   // zero g_prog
    gemm0_kernel<<<dim3(8, 512), 256, gemm_smem>>>(x, W_xh, b_h);
    probe_kernel<<<1, 32>>>();
    mega_kernel<<<128 + 2048, 256, gemm_smem>>>(W_hh, W_hy, b_y, out);
}